// round 16
// baseline (speedup 1.0000x reference)
#include <cuda_runtime.h>
#include <cuda_bf16.h>
#include <cuda_fp16.h>
#include <cstdint>

// Problem constants
#define B    4
#define C    96
#define C3   288
#define HH   256
#define WW   256
#define HWPIX 65536
#define HEADS 3
#define HC   32
#define OUT_ELEMS (B * C * HWPIX)

// ---------------- scratch (device globals) ----------------
__device__ uint16_t g_qkvh[(size_t)B * C3 * HWPIX];  // post 1x1 conv, fp16
__device__ uint16_t g_qk [(size_t)B * 192 * HWPIX];  // post dw q,k; fp16
__device__ uint16_t g_vh [(size_t)B * C * HWPIX];    // post dw v, fp16
__device__ float g_G  [B * HEADS * HC * HC];
__device__ float g_qn [B * C];
__device__ float g_kn [B * C];
__device__ float g_M  [B * C * C];
__device__ int   g_ctr;                               // gram completion counter

// ---------------- helpers ----------------
__device__ __forceinline__ uint32_t packh(float lo, float hi) {    // fp16x2
    uint32_t r;
    asm("cvt.rn.f16x2.f32 %0, %1, %2;" : "=r"(r) : "f"(hi), "f"(lo));
    return r;
}

__device__ __forceinline__ void mma16816h(float c[4], const uint32_t a[4],
                                          const uint32_t b[2]) {
    asm volatile(
        "mma.sync.aligned.m16n8k16.row.col.f32.f16.f16.f32 "
        "{%0,%1,%2,%3}, {%4,%5,%6,%7}, {%8,%9}, {%0,%1,%2,%3};"
        : "+f"(c[0]), "+f"(c[1]), "+f"(c[2]), "+f"(c[3])
        : "r"(a[0]), "r"(a[1]), "r"(a[2]), "r"(a[3]), "r"(b[0]), "r"(b[1]));
}

// ========== tensor-core GEMM (fp16 single-product, manual frag loads) ======
#define KP 104

template<int NG>
__global__ __launch_bounds__(256) void tmma_gemm(
    const float* __restrict__ Xin, const float* __restrict__ Win,
    const float* __restrict__ bias, float* __restrict__ Oout)
{
    extern __shared__ __align__(16) uint16_t sm[];
    uint16_t* sbh = sm;                       // B [128][KP] fp16
    uint16_t* sah = sm + 128 * KP;            // A [96][KP] fp16

    const int tid  = threadIdx.x;
    const int warp = tid >> 5;
    const int l    = tid & 31;
    const int b    = blockIdx.z;
    const long n0  = (long)blockIdx.x * 128;

    // fold: zero small accumulators (consumers are 2+ kernel launches later).
    // NOTE: strided loops — B*C = 384 > blockDim (256): every entry must be hit.
    if constexpr (NG == 3) {
        if (blockIdx.x == 0 && blockIdx.z == 0) {
            for (int i = tid; i < B * HEADS * HC * HC; i += 256) g_G[i] = 0.f;
            for (int i = tid; i < B * C; i += 256) { g_qn[i] = 0.f; g_kn[i] = 0.f; }
        }
    }

    const float* Wb;
    if constexpr (NG == 3) Wb = Win;
    else                   Wb = g_M + (long)b * C * C;

    // ---- B tile: X[k][px] -> smem [px][k] fp16 ----
    {
        const int px = tid & 127;
        const int kh = tid >> 7;
        if constexpr (NG == 3) {
            const float* Xb = Xin + (long)b * C * HWPIX;
            for (int k2 = kh; k2 < 48; k2 += 2) {
                const int k = k2 * 2;
                float v0 = Xb[(long)k * HWPIX + n0 + px];
                float v1 = Xb[(long)(k + 1) * HWPIX + n0 + px];
                *(uint32_t*)&sbh[px * KP + k] = packh(v0, v1);
            }
        } else {
            const uint16_t* Xp = g_vh + (long)b * C * HWPIX;
            for (int k2 = kh; k2 < 48; k2 += 2) {
                const int k = k2 * 2;
                uint32_t w0 = Xp[(long)k * HWPIX + n0 + px];
                uint32_t w1 = Xp[(long)(k + 1) * HWPIX + n0 + px];
                *(uint32_t*)&sbh[px * KP + k] = w0 | (w1 << 16);
            }
        }
    }

    const int wpx = warp * 16;
    const int lr = l >> 2;
    const int lc = (l & 3) * 2;

    for (int g = 0; g < NG; g++) {
        __syncthreads();
        const float* Wg = Wb + (long)g * 96 * 96;
        for (int i = tid; i < 96 * 48; i += 256) {
            int m = i / 48, kp_ = (i - m * 48) * 2;
            float2 wv = *(const float2*)&Wg[m * 96 + kp_];
            *(uint32_t*)&sah[m * KP + kp_] = packh(wv.x, wv.y);
        }
        __syncthreads();

        float c[6][2][4];
#pragma unroll
        for (int mt = 0; mt < 6; mt++)
#pragma unroll
            for (int nt = 0; nt < 2; nt++)
#pragma unroll
                for (int j = 0; j < 4; j++) c[mt][nt][j] = 0.f;

#pragma unroll
        for (int s = 0; s < 6; s++) {
            const int k0 = s * 16;
            uint32_t bh[2][2];
#pragma unroll
            for (int nt = 0; nt < 2; nt++) {
                const int n = wpx + nt * 8 + lr;
                bh[nt][0] = *(const uint32_t*)&sbh[n * KP + k0 + lc];
                bh[nt][1] = *(const uint32_t*)&sbh[n * KP + k0 + lc + 8];
            }
#pragma unroll
            for (int mt = 0; mt < 6; mt++) {
                const int r = mt * 16 + lr;
                uint32_t ah[4];
                ah[0] = *(const uint32_t*)&sah[r * KP + k0 + lc];
                ah[1] = *(const uint32_t*)&sah[(r + 8) * KP + k0 + lc];
                ah[2] = *(const uint32_t*)&sah[r * KP + k0 + lc + 8];
                ah[3] = *(const uint32_t*)&sah[(r + 8) * KP + k0 + lc + 8];
#pragma unroll
                for (int nt = 0; nt < 2; nt++)
                    mma16816h(c[mt][nt], ah, bh[nt]);
            }
        }

        // ---- epilogue ----
#pragma unroll
        for (int mt = 0; mt < 6; mt++) {
#pragma unroll
            for (int nt = 0; nt < 2; nt++) {
                const int ch0 = g * 96 + mt * 16 + lr;
                const long px = n0 + wpx + nt * 8 + lc;
                float b0 = __ldg(&bias[ch0]);
                float b1 = __ldg(&bias[ch0 + 8]);
                if constexpr (NG == 3) {
                    uint16_t* Oh = g_qkvh + (long)b * C3 * HWPIX;
                    *(uint32_t*)&Oh[(long)ch0 * HWPIX + px] =
                        packh(c[mt][nt][0] + b0, c[mt][nt][1] + b0);
                    *(uint32_t*)&Oh[(long)(ch0 + 8) * HWPIX + px] =
                        packh(c[mt][nt][2] + b1, c[mt][nt][3] + b1);
                } else {
                    float* Ob = Oout + (long)b * C * HWPIX;
                    float2 v0 = { c[mt][nt][0] + b0, c[mt][nt][1] + b0 };
                    float2 v1 = { c[mt][nt][2] + b1, c[mt][nt][3] + b1 };
                    *(float2*)&Ob[(long)ch0 * HWPIX + px] = v0;
                    *(float2*)&Ob[(long)(ch0 + 8) * HWPIX + px] = v1;
                }
            }
        }
    }
}

// ---------------- K2: depthwise conv, 8 px/thread (R13) ----------
__global__ __launch_bounds__(128) void dwconv(
    const float* __restrict__ dw_w, const float* __restrict__ dw_b)
{
    const int tx = threadIdx.x;         // 0..31
    const int ty = threadIdx.y;         // 0..3
    const int ch = blockIdx.y;
    const int b  = blockIdx.z;
    const int col0 = tx * 8;
    const __half* P = (const __half*)(g_qkvh + ((long)(b * C3 + ch)) * HWPIX);

    float w[9];
#pragma unroll
    for (int t = 0; t < 9; t++) w[t] = __ldg(&dw_w[ch * 9 + t]);
    const float bias = __ldg(&dw_b[ch]);

    const int y0 = blockIdx.x * 32 + ty * 8;

    float A[10], Bw[10], Cw[10];
    auto loadrow = [&](int y, float* v) {
        if ((unsigned)y < 256u) {
            const __half* row = P + y * WW + col0;
            uint4 m = *(const uint4*)row;
            __half2 p0 = *(__half2*)&m.x;
            __half2 p1 = *(__half2*)&m.y;
            __half2 p2 = *(__half2*)&m.z;
            __half2 p3 = *(__half2*)&m.w;
            v[1] = __low2float(p0);  v[2] = __high2float(p0);
            v[3] = __low2float(p1);  v[4] = __high2float(p1);
            v[5] = __low2float(p2);  v[6] = __high2float(p2);
            v[7] = __low2float(p3);  v[8] = __high2float(p3);
            v[0] = (col0 > 0)   ? __half2float(__ldg(row - 1)) : 0.f;
            v[9] = (col0 < 248) ? __half2float(__ldg(row + 8)) : 0.f;
        } else {
#pragma unroll
            for (int j = 0; j < 10; j++) v[j] = 0.f;
        }
    };
    loadrow(y0 - 1, A);
    loadrow(y0,     Bw);

    uint16_t* O = (ch < 192) ? (g_qk + ((long)(b * 192 + ch)) * HWPIX)
                             : (g_vh + ((long)(b * C + (ch - 192))) * HWPIX);

    float ss = 0.f;
#pragma unroll
    for (int dy = 0; dy < 8; dy++) {
        loadrow(y0 + dy + 1, Cw);
        float o0[8];
#pragma unroll
        for (int j = 0; j < 8; j++) {
            o0[j] = bias
                + w[0] * A[j]  + w[1] * A[j + 1]  + w[2] * A[j + 2]
                + w[3] * Bw[j] + w[4] * Bw[j + 1] + w[5] * Bw[j + 2]
                + w[6] * Cw[j] + w[7] * Cw[j + 1] + w[8] * Cw[j + 2];
            ss += o0[j] * o0[j];
        }
        uint4 st;
        st.x = packh(o0[0], o0[1]);
        st.y = packh(o0[2], o0[3]);
        st.z = packh(o0[4], o0[5]);
        st.w = packh(o0[6], o0[7]);
        *(uint4*)&O[(y0 + dy) * WW + col0] = st;
#pragma unroll
        for (int j = 0; j < 10; j++) { A[j] = Bw[j]; Bw[j] = Cw[j]; }
    }

    if (ch < 192) {
        const int tid = ty * 32 + tx;
#pragma unroll
        for (int o = 16; o; o >>= 1) ss += __shfl_down_sync(0xffffffffu, ss, o);
        __shared__ float red[4];
        if ((tid & 31) == 0) red[tid >> 5] = ss;
        __syncthreads();
        if (tid == 0) {
            float t = red[0] + red[1] + red[2] + red[3];
            float* dst = (ch < 96) ? &g_qn[b * C + ch] : &g_kn[b * C + ch - 96];
            atomicAdd(dst, t);
        }
    }
}

// ---------------- K3: Gram + (last block) fused softmax & M ----------------
#define GP32 132
#define GRAM_BLOCKS (64 * HEADS * B)
__global__ __launch_bounds__(256) void gram_mma(
    const float* __restrict__ proj_w, float* __restrict__ out)
{
    extern __shared__ uint32_t gsm[];
    uint32_t* qs = gsm;
    uint32_t* ks = gsm + 32 * GP32;
    float* red = (float*)gsm;

    const int chunk = blockIdx.x, h = blockIdx.y, b = blockIdx.z;
    const uint16_t* qg = g_qk + ((long)(b * 192 + h * HC)) * HWPIX;
    const uint16_t* kg = g_qk + ((long)(b * 192 + 96 + h * HC)) * HWPIX;
    const int tid = threadIdx.x, w = tid >> 5, l = tid & 31;
    const int lr = l >> 2, lq = l & 3;

    float c[2][4][4];
#pragma unroll
    for (int mt = 0; mt < 2; mt++)
#pragma unroll
        for (int nt = 0; nt < 4; nt++)
#pragma unroll
            for (int j = 0; j < 4; j++) c[mt][nt][j] = 0.f;

    const long base = (long)chunk * 1024;
    for (int s = 0; s < 4; s++) {
        const long n = base + s * 256;
        __syncthreads();
#pragma unroll
        for (int e = 0; e < 4; e++) {
            int i4 = e * 256 + tid;
            int ch = i4 >> 5, u = i4 & 31;
            *(uint4*)&qs[ch * GP32 + u * 4] = *(const uint4*)&qg[(long)ch * HWPIX + n + u * 8];
            *(uint4*)&ks[ch * GP32 + u * 4] = *(const uint4*)&kg[(long)ch * HWPIX + n + u * 8];
        }
        __syncthreads();

        const int pxw = w * 32;
#pragma unroll
        for (int st = 0; st < 2; st++) {
            const int wb = (pxw + st * 16) >> 1;
            uint32_t bh[4][2];
#pragma unroll
            for (int nt = 0; nt < 4; nt++) {
                bh[nt][0] = ks[(nt * 8 + lr) * GP32 + wb + lq];
                bh[nt][1] = ks[(nt * 8 + lr) * GP32 + wb + 4 + lq];
            }
#pragma unroll
            for (int mt = 0; mt < 2; mt++) {
                uint32_t a[4];
                a[0] = qs[(mt * 16 + lr) * GP32 + wb + lq];
                a[1] = qs[(mt * 16 + 8 + lr) * GP32 + wb + lq];
                a[2] = qs[(mt * 16 + lr) * GP32 + wb + 4 + lq];
                a[3] = qs[(mt * 16 + 8 + lr) * GP32 + wb + 4 + lq];
#pragma unroll
                for (int nt = 0; nt < 4; nt++)
                    mma16816h(c[mt][nt], a, bh[nt]);
            }
        }
    }

    __syncthreads();
#pragma unroll
    for (int mt = 0; mt < 2; mt++)
#pragma unroll
        for (int nt = 0; nt < 4; nt++)
#pragma unroll
            for (int j = 0; j < 4; j++) {
                int row = mt * 16 + lr + ((j >> 1) << 3);
                int cl  = nt * 8 + lq * 2 + (j & 1);
                red[w * 1024 + row * 32 + cl] = c[mt][nt][j];
            }
    __syncthreads();
    float* Gp = g_G + (long)(b * HEADS + h) * HC * HC;
    for (int i = tid; i < 1024; i += 256) {
        float sum = 0.f;
#pragma unroll
        for (int ww = 0; ww < 8; ww++) sum += red[ww * 1024 + i];
        atomicAdd(&Gp[i], sum);
    }

    // ---- last-block epilogue: softmax + M for all batches ----
    __shared__ int s_last;
    __syncthreads();
    if (tid == 0) {
        __threadfence();
        int p = atomicAdd(&g_ctr, 1);
        s_last = (p == GRAM_BLOCKS - 1) ? 1 : 0;
    }
    __syncthreads();
    if (!s_last) return;
    __threadfence();   // acquire: all G atomics visible

    // softmax: 384 (b,h,c) rows -> out tail
    for (int rowi = tid; rowi < B * HEADS * HC; rowi += 256) {
        const int bb = rowi / (HEADS * HC);
        const int rem = rowi - bb * HEADS * HC;
        const int hh = rem >> 5, cc = rem & 31;
        float nq = fmaxf(sqrtf(g_qn[bb * C + hh * HC + cc]), 1e-12f);
        float v[32];
#pragma unroll
        for (int d = 0; d < 32; d++) {
            float nk = fmaxf(sqrtf(g_kn[bb * C + hh * HC + d]), 1e-12f);
            v[d] = g_G[((bb * HEADS + hh) * HC + cc) * HC + d] / (nq * nk);
        }
        float m = -1e30f;
#pragma unroll
        for (int d = 0; d < 32; d++) m = fmaxf(m, v[d]);
        float s = 0.f;
#pragma unroll
        for (int d = 0; d < 32; d++) { v[d] = expf(v[d] - m); s += v[d]; }
        float inv = 1.f / s;
        float* ap = out + OUT_ELEMS + (long)(bb * HEADS + hh) * (HC * HC) + cc * HC;
#pragma unroll
        for (int d = 0; d < 32; d++) ap[d] = v[d] * inv;
    }
    __syncthreads();

    // M[b] = proj_w @ blockdiag(attn), attn read back from out tail (L2-hot)
    const float* attn = out + OUT_ELEMS;
    for (int idx = tid; idx < B * C * C; idx += 256) {
        int bb = idx / (C * C);
        int r  = idx - bb * C * C;
        int o = r / 96, g = r % 96;
        int hh = g >> 5, d = g & 31;
        const float* prow = proj_w + o * 96 + hh * HC;
        const float* acol = attn + (long)(bb * HEADS + hh) * (HC * HC) + d;
        float s = 0.f;
#pragma unroll
        for (int cc2 = 0; cc2 < 32; cc2++) s += prow[cc2] * acol[cc2 * 32];
        g_M[idx] = s;
    }
    if (tid == 0) g_ctr = 0;   // reset for next graph replay
}

// ---------------- launch ----------------
extern "C" void kernel_launch(void* const* d_in, const int* in_sizes, int n_in,
                              void* d_out, int out_size)
{
    const float* x      = (const float*)d_in[0];
    const float* qkv_w  = (const float*)d_in[1];
    const float* qkv_b  = (const float*)d_in[2];
    const float* dw_w   = (const float*)d_in[3];
    const float* dw_b   = (const float*)d_in[4];
    const float* proj_w = (const float*)d_in[5];
    const float* proj_b = (const float*)d_in[6];
    float* out = (float*)d_out;

    const int smem_gemm = (128 * KP + 96 * KP) * 2;           // 46,592 B
    const int smem_gram = 2 * 32 * GP32 * 4;                  // 33,792 B
    cudaFuncSetAttribute(tmma_gemm<3>, cudaFuncAttributeMaxDynamicSharedMemorySize, smem_gemm);
    cudaFuncSetAttribute(tmma_gemm<1>, cudaFuncAttributeMaxDynamicSharedMemorySize, smem_gemm);
    cudaFuncSetAttribute(gram_mma,     cudaFuncAttributeMaxDynamicSharedMemorySize, smem_gram);

    tmma_gemm<3><<<dim3(512, 1, B), 256, smem_gemm>>>(x, qkv_w, qkv_b, nullptr);
    dwconv<<<dim3(8, C3, B), dim3(32, 4)>>>(dw_w, dw_b);
    gram_mma<<<dim3(64, HEADS, B), 256, smem_gram>>>(proj_w, out);
    tmma_gemm<1><<<dim3(512, 1, B), 256, smem_gemm>>>(nullptr, nullptr, proj_b, out);
}

// round 17
// speedup vs baseline: 1.1402x; 1.1402x over previous
#include <cuda_runtime.h>
#include <cuda_bf16.h>
#include <cuda_fp16.h>
#include <cstdint>

// Problem constants
#define B    4
#define C    96
#define C3   288
#define HH   256
#define WW   256
#define HWPIX 65536
#define HEADS 3
#define HC   32
#define OUT_ELEMS (B * C * HWPIX)

// ---------------- scratch (device globals) ----------------
__device__ uint16_t g_qkvh[(size_t)B * C3 * HWPIX];  // post 1x1 conv, fp16
__device__ uint16_t g_qk [(size_t)B * 192 * HWPIX];  // post dw q,k; fp16
__device__ uint16_t g_vh [(size_t)B * C * HWPIX];    // post dw v, fp16
__device__ float g_G  [B * HEADS * HC * HC];
__device__ float g_qn [B * C];
__device__ float g_kn [B * C];
__device__ float g_M  [B * C * C];

// ---------------- helpers ----------------
__device__ __forceinline__ uint32_t packh(float lo, float hi) {    // fp16x2
    uint32_t r;
    asm("cvt.rn.f16x2.f32 %0, %1, %2;" : "=r"(r) : "f"(hi), "f"(lo));
    return r;
}

__device__ __forceinline__ void mma16816h(float c[4], const uint32_t a[4],
                                          const uint32_t b[2]) {
    asm volatile(
        "mma.sync.aligned.m16n8k16.row.col.f32.f16.f16.f32 "
        "{%0,%1,%2,%3}, {%4,%5,%6,%7}, {%8,%9}, {%0,%1,%2,%3};"
        : "+f"(c[0]), "+f"(c[1]), "+f"(c[2]), "+f"(c[3])
        : "r"(a[0]), "r"(a[1]), "r"(a[2]), "r"(a[3]), "r"(b[0]), "r"(b[1]));
}

// ========== tensor-core GEMM (fp16 single-product, manual frag loads) ======
#define KP 104

template<int NG>
__global__ __launch_bounds__(256) void tmma_gemm(
    const float* __restrict__ Xin, const float* __restrict__ Win,
    const float* __restrict__ bias, float* __restrict__ Oout)
{
    extern __shared__ __align__(16) uint16_t sm[];
    uint16_t* sbh = sm;                       // B [128][KP] fp16
    uint16_t* sah = sm + 128 * KP;            // A [96][KP] fp16

    const int tid  = threadIdx.x;
    const int warp = tid >> 5;
    const int l    = tid & 31;
    const int b    = blockIdx.z;
    const long n0  = (long)blockIdx.x * 128;

    // fold: zero small accumulators (consumers run 2+ launches later).
    // Strided loops: B*C = 384 > blockDim (256) — every entry must be hit.
    if constexpr (NG == 3) {
        if (blockIdx.x == 0 && blockIdx.z == 0) {
            for (int i = tid; i < B * HEADS * HC * HC; i += 256) g_G[i] = 0.f;
            for (int i = tid; i < B * C; i += 256) { g_qn[i] = 0.f; g_kn[i] = 0.f; }
        }
    }

    const float* Wb;
    if constexpr (NG == 3) Wb = Win;
    else                   Wb = g_M + (long)b * C * C;

    // ---- B tile: X[k][px] -> smem [px][k] fp16 ----
    {
        const int px = tid & 127;
        const int kh = tid >> 7;
        if constexpr (NG == 3) {
            const float* Xb = Xin + (long)b * C * HWPIX;
            for (int k2 = kh; k2 < 48; k2 += 2) {
                const int k = k2 * 2;
                float v0 = Xb[(long)k * HWPIX + n0 + px];
                float v1 = Xb[(long)(k + 1) * HWPIX + n0 + px];
                *(uint32_t*)&sbh[px * KP + k] = packh(v0, v1);
            }
        } else {
            const uint16_t* Xp = g_vh + (long)b * C * HWPIX;
            for (int k2 = kh; k2 < 48; k2 += 2) {
                const int k = k2 * 2;
                uint32_t w0 = Xp[(long)k * HWPIX + n0 + px];
                uint32_t w1 = Xp[(long)(k + 1) * HWPIX + n0 + px];
                *(uint32_t*)&sbh[px * KP + k] = w0 | (w1 << 16);
            }
        }
    }

    const int wpx = warp * 16;
    const int lr = l >> 2;
    const int lc = (l & 3) * 2;

    for (int g = 0; g < NG; g++) {
        __syncthreads();
        const float* Wg = Wb + (long)g * 96 * 96;
        for (int i = tid; i < 96 * 48; i += 256) {
            int m = i / 48, kp_ = (i - m * 48) * 2;
            float2 wv = *(const float2*)&Wg[m * 96 + kp_];
            *(uint32_t*)&sah[m * KP + kp_] = packh(wv.x, wv.y);
        }
        __syncthreads();

        float c[6][2][4];
#pragma unroll
        for (int mt = 0; mt < 6; mt++)
#pragma unroll
            for (int nt = 0; nt < 2; nt++)
#pragma unroll
                for (int j = 0; j < 4; j++) c[mt][nt][j] = 0.f;

#pragma unroll
        for (int s = 0; s < 6; s++) {
            const int k0 = s * 16;
            uint32_t bh[2][2];
#pragma unroll
            for (int nt = 0; nt < 2; nt++) {
                const int n = wpx + nt * 8 + lr;
                bh[nt][0] = *(const uint32_t*)&sbh[n * KP + k0 + lc];
                bh[nt][1] = *(const uint32_t*)&sbh[n * KP + k0 + lc + 8];
            }
#pragma unroll
            for (int mt = 0; mt < 6; mt++) {
                const int r = mt * 16 + lr;
                uint32_t ah[4];
                ah[0] = *(const uint32_t*)&sah[r * KP + k0 + lc];
                ah[1] = *(const uint32_t*)&sah[(r + 8) * KP + k0 + lc];
                ah[2] = *(const uint32_t*)&sah[r * KP + k0 + lc + 8];
                ah[3] = *(const uint32_t*)&sah[(r + 8) * KP + k0 + lc + 8];
#pragma unroll
                for (int nt = 0; nt < 2; nt++)
                    mma16816h(c[mt][nt], ah, bh[nt]);
            }
        }

        // ---- epilogue ----
#pragma unroll
        for (int mt = 0; mt < 6; mt++) {
#pragma unroll
            for (int nt = 0; nt < 2; nt++) {
                const int ch0 = g * 96 + mt * 16 + lr;
                const long px = n0 + wpx + nt * 8 + lc;
                float b0 = __ldg(&bias[ch0]);
                float b1 = __ldg(&bias[ch0 + 8]);
                if constexpr (NG == 3) {
                    uint16_t* Oh = g_qkvh + (long)b * C3 * HWPIX;
                    *(uint32_t*)&Oh[(long)ch0 * HWPIX + px] =
                        packh(c[mt][nt][0] + b0, c[mt][nt][1] + b0);
                    *(uint32_t*)&Oh[(long)(ch0 + 8) * HWPIX + px] =
                        packh(c[mt][nt][2] + b1, c[mt][nt][3] + b1);
                } else {
                    float* Ob = Oout + (long)b * C * HWPIX;
                    float2 v0 = { c[mt][nt][0] + b0, c[mt][nt][1] + b0 };
                    float2 v1 = { c[mt][nt][2] + b1, c[mt][nt][3] + b1 };
                    *(float2*)&Ob[(long)ch0 * HWPIX + px] = v0;
                    *(float2*)&Ob[(long)(ch0 + 8) * HWPIX + px] = v1;
                }
            }
        }
    }
}

// ---------------- K2: depthwise conv, 8 px/thread (R13) ----------
__global__ __launch_bounds__(128) void dwconv(
    const float* __restrict__ dw_w, const float* __restrict__ dw_b)
{
    const int tx = threadIdx.x;         // 0..31
    const int ty = threadIdx.y;         // 0..3
    const int ch = blockIdx.y;
    const int b  = blockIdx.z;
    const int col0 = tx * 8;
    const __half* P = (const __half*)(g_qkvh + ((long)(b * C3 + ch)) * HWPIX);

    float w[9];
#pragma unroll
    for (int t = 0; t < 9; t++) w[t] = __ldg(&dw_w[ch * 9 + t]);
    const float bias = __ldg(&dw_b[ch]);

    const int y0 = blockIdx.x * 32 + ty * 8;

    float A[10], Bw[10], Cw[10];
    auto loadrow = [&](int y, float* v) {
        if ((unsigned)y < 256u) {
            const __half* row = P + y * WW + col0;
            uint4 m = *(const uint4*)row;
            __half2 p0 = *(__half2*)&m.x;
            __half2 p1 = *(__half2*)&m.y;
            __half2 p2 = *(__half2*)&m.z;
            __half2 p3 = *(__half2*)&m.w;
            v[1] = __low2float(p0);  v[2] = __high2float(p0);
            v[3] = __low2float(p1);  v[4] = __high2float(p1);
            v[5] = __low2float(p2);  v[6] = __high2float(p2);
            v[7] = __low2float(p3);  v[8] = __high2float(p3);
            v[0] = (col0 > 0)   ? __half2float(__ldg(row - 1)) : 0.f;
            v[9] = (col0 < 248) ? __half2float(__ldg(row + 8)) : 0.f;
        } else {
#pragma unroll
            for (int j = 0; j < 10; j++) v[j] = 0.f;
        }
    };
    loadrow(y0 - 1, A);
    loadrow(y0,     Bw);

    uint16_t* O = (ch < 192) ? (g_qk + ((long)(b * 192 + ch)) * HWPIX)
                             : (g_vh + ((long)(b * C + (ch - 192))) * HWPIX);

    float ss = 0.f;
#pragma unroll
    for (int dy = 0; dy < 8; dy++) {
        loadrow(y0 + dy + 1, Cw);
        float o0[8];
#pragma unroll
        for (int j = 0; j < 8; j++) {
            o0[j] = bias
                + w[0] * A[j]  + w[1] * A[j + 1]  + w[2] * A[j + 2]
                + w[3] * Bw[j] + w[4] * Bw[j + 1] + w[5] * Bw[j + 2]
                + w[6] * Cw[j] + w[7] * Cw[j + 1] + w[8] * Cw[j + 2];
            ss += o0[j] * o0[j];
        }
        uint4 st;
        st.x = packh(o0[0], o0[1]);
        st.y = packh(o0[2], o0[3]);
        st.z = packh(o0[4], o0[5]);
        st.w = packh(o0[6], o0[7]);
        *(uint4*)&O[(y0 + dy) * WW + col0] = st;
#pragma unroll
        for (int j = 0; j < 10; j++) { A[j] = Bw[j]; Bw[j] = Cw[j]; }
    }

    if (ch < 192) {
        const int tid = ty * 32 + tx;
#pragma unroll
        for (int o = 16; o; o >>= 1) ss += __shfl_down_sync(0xffffffffu, ss, o);
        __shared__ float red[4];
        if ((tid & 31) == 0) red[tid >> 5] = ss;
        __syncthreads();
        if (tid == 0) {
            float t = red[0] + red[1] + red[2] + red[3];
            float* dst = (ch < 96) ? &g_qn[b * C + ch] : &g_kn[b * C + ch - 96];
            atomicAdd(dst, t);
        }
    }
}

// ---------------- K3: Gram via fp16 mma.sync (single product) — R13 --------
#define GP32 132
__global__ __launch_bounds__(256) void gram_mma()
{
    extern __shared__ uint32_t gsm[];
    uint32_t* qs = gsm;
    uint32_t* ks = gsm + 32 * GP32;
    float* red = (float*)gsm;

    const int chunk = blockIdx.x, h = blockIdx.y, b = blockIdx.z;
    const uint16_t* qg = g_qk + ((long)(b * 192 + h * HC)) * HWPIX;
    const uint16_t* kg = g_qk + ((long)(b * 192 + 96 + h * HC)) * HWPIX;
    const int tid = threadIdx.x, w = tid >> 5, l = tid & 31;
    const int lr = l >> 2, lq = l & 3;

    float c[2][4][4];
#pragma unroll
    for (int mt = 0; mt < 2; mt++)
#pragma unroll
        for (int nt = 0; nt < 4; nt++)
#pragma unroll
            for (int j = 0; j < 4; j++) c[mt][nt][j] = 0.f;

    const long base = (long)chunk * 1024;
    for (int s = 0; s < 4; s++) {
        const long n = base + s * 256;
        __syncthreads();
#pragma unroll
        for (int e = 0; e < 4; e++) {
            int i4 = e * 256 + tid;
            int ch = i4 >> 5, u = i4 & 31;
            *(uint4*)&qs[ch * GP32 + u * 4] = *(const uint4*)&qg[(long)ch * HWPIX + n + u * 8];
            *(uint4*)&ks[ch * GP32 + u * 4] = *(const uint4*)&kg[(long)ch * HWPIX + n + u * 8];
        }
        __syncthreads();

        const int pxw = w * 32;
#pragma unroll
        for (int st = 0; st < 2; st++) {
            const int wb = (pxw + st * 16) >> 1;
            uint32_t bh[4][2];
#pragma unroll
            for (int nt = 0; nt < 4; nt++) {
                bh[nt][0] = ks[(nt * 8 + lr) * GP32 + wb + lq];
                bh[nt][1] = ks[(nt * 8 + lr) * GP32 + wb + 4 + lq];
            }
#pragma unroll
            for (int mt = 0; mt < 2; mt++) {
                uint32_t a[4];
                a[0] = qs[(mt * 16 + lr) * GP32 + wb + lq];
                a[1] = qs[(mt * 16 + 8 + lr) * GP32 + wb + lq];
                a[2] = qs[(mt * 16 + lr) * GP32 + wb + 4 + lq];
                a[3] = qs[(mt * 16 + 8 + lr) * GP32 + wb + 4 + lq];
#pragma unroll
                for (int nt = 0; nt < 4; nt++)
                    mma16816h(c[mt][nt], a, bh[nt]);
            }
        }
    }

    __syncthreads();
#pragma unroll
    for (int mt = 0; mt < 2; mt++)
#pragma unroll
        for (int nt = 0; nt < 4; nt++)
#pragma unroll
            for (int j = 0; j < 4; j++) {
                int row = mt * 16 + lr + ((j >> 1) << 3);
                int cl  = nt * 8 + lq * 2 + (j & 1);
                red[w * 1024 + row * 32 + cl] = c[mt][nt][j];
            }
    __syncthreads();
    float* Gp = g_G + (long)(b * HEADS + h) * HC * HC;
    for (int i = tid; i < 1024; i += 256) {
        float sum = 0.f;
#pragma unroll
        for (int ww = 0; ww < 8; ww++) sum += red[ww * 1024 + i];
        atomicAdd(&Gp[i], sum);
    }
}

// ---------------- K3b: FUSED softmax + M (grid 4, block 288) — R13 ----------
__global__ __launch_bounds__(288) void softmax_M(
    const float* __restrict__ proj_w, float* __restrict__ out)
{
    __shared__ float attn_s[HEADS * HC * HC];   // [h][c][d]
    const int b = blockIdx.x;
    const int tid = threadIdx.x;

    if (tid < 96) {
        const int h = tid >> 5, c = tid & 31;
        float nq = fmaxf(sqrtf(g_qn[b * C + h * HC + c]), 1e-12f);
        float v[32];
#pragma unroll
        for (int d = 0; d < 32; d++) {
            float nk = fmaxf(sqrtf(g_kn[b * C + h * HC + d]), 1e-12f);
            v[d] = g_G[((b * HEADS + h) * HC + c) * HC + d] / (nq * nk);
        }
        float m = -1e30f;
#pragma unroll
        for (int d = 0; d < 32; d++) m = fmaxf(m, v[d]);
        float s = 0.f;
#pragma unroll
        for (int d = 0; d < 32; d++) { v[d] = expf(v[d] - m); s += v[d]; }
        float inv = 1.f / s;
        float* ap = out + OUT_ELEMS + (long)(b * HEADS + h) * (HC * HC) + c * HC;
#pragma unroll
        for (int d = 0; d < 32; d++) {
            float av = v[d] * inv;
            ap[d] = av;
            attn_s[(h * HC + c) * HC + d] = av;
        }
    }
    __syncthreads();

#pragma unroll
    for (int e = 0; e < 32; e++) {
        int idx = e * 288 + tid;
        int o = idx / 96, g = idx % 96;
        int h = g >> 5, d = g & 31;
        const float* prow = proj_w + o * 96 + h * HC;
        const float* acol = attn_s + h * HC * HC + d;
        float s = 0.f;
#pragma unroll
        for (int cc = 0; cc < 32; cc++) s += prow[cc] * acol[cc * 32];
        g_M[(long)b * C * C + idx] = s;
    }
}

// ---------------- launch ----------------
extern "C" void kernel_launch(void* const* d_in, const int* in_sizes, int n_in,
                              void* d_out, int out_size)
{
    const float* x      = (const float*)d_in[0];
    const float* qkv_w  = (const float*)d_in[1];
    const float* qkv_b  = (const float*)d_in[2];
    const float* dw_w   = (const float*)d_in[3];
    const float* dw_b   = (const float*)d_in[4];
    const float* proj_w = (const float*)d_in[5];
    const float* proj_b = (const float*)d_in[6];
    float* out = (float*)d_out;

    const int smem_gemm = (128 * KP + 96 * KP) * 2;           // 46,592 B
    const int smem_gram = 2 * 32 * GP32 * 4;                  // 33,792 B
    cudaFuncSetAttribute(tmma_gemm<3>, cudaFuncAttributeMaxDynamicSharedMemorySize, smem_gemm);
    cudaFuncSetAttribute(tmma_gemm<1>, cudaFuncAttributeMaxDynamicSharedMemorySize, smem_gemm);
    cudaFuncSetAttribute(gram_mma,     cudaFuncAttributeMaxDynamicSharedMemorySize, smem_gram);

    tmma_gemm<3><<<dim3(512, 1, B), 256, smem_gemm>>>(x, qkv_w, qkv_b, nullptr);
    dwconv<<<dim3(8, C3, B), dim3(32, 4)>>>(dw_w, dw_b);
    gram_mma<<<dim3(64, HEADS, B), 256, smem_gram>>>();
    softmax_M<<<B, 288>>>(proj_w, out);
    tmma_gemm<1><<<dim3(512, 1, B), 256, smem_gemm>>>(nullptr, nullptr, proj_b, out);
}